// round 7
// baseline (speedup 1.0000x reference)
#include <cuda_runtime.h>
#include <cuda_fp16.h>
#include <cstdint>

// ---------------- problem constants ----------------
#define BATCH 4
#define SEQ   2048
#define DMODEL 1024
#define NHEAD 16
#define DHEAD 64
#define FFDIM 4096
#define BS (BATCH*SEQ)
#define QKVN 3072
#define QSCALE 0.1803368801111204f   // log2(e) / sqrt(64)

// ---------------- device scratch ----------------
__device__ __half g_wqkvT[(size_t)QKVN * DMODEL];   // [N=3072][K=1024] (q part pre-scaled)
__device__ float  g_bqkv [QKVN];                    // q part pre-scaled
__device__ __half g_woT  [(size_t)DMODEL * DMODEL];
__device__ __half g_w1T  [(size_t)FFDIM * DMODEL];
__device__ __half g_w2T  [(size_t)DMODEL * FFDIM];
__device__ __half g_xh   [(size_t)BS * DMODEL];
__device__ __half g_qkvh [(size_t)BS * QKVN];
__device__ __half g_attnh[(size_t)BS * DMODEL];
__device__ float  g_t1   [(size_t)BS * DMODEL];
__device__ float  g_y    [(size_t)BS * DMODEL];
__device__ __half g_yh   [(size_t)BS * DMODEL];
__device__ __half g_ff1h [(size_t)BS * FFDIM];
__device__ float  g_ff2  [(size_t)BS * DMODEL];

// ---------------- helpers ----------------
__device__ __forceinline__ uint32_t smem_u32(const void* p) {
    uint32_t a;
    asm("{ .reg .u64 t; cvta.to.shared.u64 t, %1; cvt.u32.u64 %0, t; }" : "=r"(a) : "l"(p));
    return a;
}
__device__ __forceinline__ void cp16(uint32_t sdst, const void* gsrc) {
    asm volatile("cp.async.cg.shared.global [%0], [%1], 16;" :: "r"(sdst), "l"(gsrc) : "memory");
}
__device__ __forceinline__ void mma_f16(float* c, const uint32_t* a, const uint32_t* b) {
    asm volatile(
        "mma.sync.aligned.m16n8k16.row.col.f32.f16.f16.f32 "
        "{%0,%1,%2,%3}, {%4,%5,%6,%7}, {%8,%9}, {%0,%1,%2,%3};"
        : "+f"(c[0]), "+f"(c[1]), "+f"(c[2]), "+f"(c[3])
        : "r"(a[0]), "r"(a[1]), "r"(a[2]), "r"(a[3]), "r"(b[0]), "r"(b[1]));
}
#define LDSM4(r0, r1, r2, r3, addr) \
    asm volatile("ldmatrix.sync.aligned.m8n8.x4.shared.b16 {%0,%1,%2,%3}, [%4];" \
                 : "=r"(r0), "=r"(r1), "=r"(r2), "=r"(r3) : "r"(addr))
#define LDSM4T(r0, r1, r2, r3, addr) \
    asm volatile("ldmatrix.sync.aligned.m8n8.x4.trans.shared.b16 {%0,%1,%2,%3}, [%4];" \
                 : "=r"(r0), "=r"(r1), "=r"(r2), "=r"(r3) : "r"(addr))
__device__ __forceinline__ uint32_t h2pack(float a, float b) {
    __half2 t = __floats2half2_rn(a, b);
    return *reinterpret_cast<uint32_t*>(&t);
}

// ---------------- weight prep (coalesced both sides via smem transpose) ----------------
// wq/wk/wv: [H][D][DH] -> g_wqkvT[3*1024 rows][1024]; q pre-scaled by QSCALE
__global__ void pack_wqkv_t(const float* __restrict__ wq, const float* __restrict__ wk,
                            const float* __restrict__ wv)
{
    __shared__ float t[3][32][33];
    const int h = blockIdx.z;
    const int e0 = blockIdx.x * 32, d0 = blockIdx.y * 32;
    const int x = threadIdx.x, y = threadIdx.y;   // 32 x 8
    const size_t src_base = (size_t)h * DMODEL * DHEAD;
#pragma unroll
    for (int i = 0; i < 32; i += 8) {
        size_t off = src_base + (size_t)(d0 + y + i) * DHEAD + e0 + x;
        t[0][y + i][x] = wq[off];
        t[1][y + i][x] = wk[off];
        t[2][y + i][x] = wv[off];
    }
    __syncthreads();
#pragma unroll
    for (int i = 0; i < 32; i += 8) {
        int row = h * DHEAD + e0 + y + i;
        g_wqkvT[(size_t)row * DMODEL + d0 + x]          = __float2half(t[0][x][y + i] * QSCALE);
        g_wqkvT[(size_t)(1024 + row) * DMODEL + d0 + x] = __float2half(t[1][x][y + i]);
        g_wqkvT[(size_t)(2048 + row) * DMODEL + d0 + x] = __float2half(t[2][x][y + i]);
    }
}

__global__ void pack_bqkv(const float* __restrict__ bq, const float* __restrict__ bk,
                          const float* __restrict__ bv)
{
    int i = blockIdx.x * blockDim.x + threadIdx.x;
    if (i < NHEAD * DHEAD) {
        g_bqkv[i]        = bq[i] * QSCALE;
        g_bqkv[1024 + i] = bk[i];
        g_bqkv[2048 + i] = bv[i];
    }
}

// transpose fp32 [R][C] -> half [C][R]
__global__ void transpose_h(const float* __restrict__ in, __half* __restrict__ out,
                            int R, int C)
{
    __shared__ float t[32][33];
    int c0 = blockIdx.x * 32, r0 = blockIdx.y * 32;
    int x = threadIdx.x, y = threadIdx.y;   // 32 x 8
#pragma unroll
    for (int i = 0; i < 32; i += 8)
        t[y + i][x] = in[(size_t)(r0 + y + i) * C + c0 + x];
    __syncthreads();
#pragma unroll
    for (int i = 0; i < 32; i += 8)
        out[(size_t)(c0 + y + i) * R + r0 + x] = __float2half(t[x][y + i]);
}

__global__ void f2h_copy(const float* __restrict__ in, __half* __restrict__ out, int n4)
{
    int i = blockIdx.x * blockDim.x + threadIdx.x;
    if (i < n4) {
        float4 v = ((const float4*)in)[i];
        __half2 a = __floats2half2_rn(v.x, v.y);
        __half2 b = __floats2half2_rn(v.z, v.w);
        *(uint2*)(out + (size_t)i * 4) = make_uint2(*(uint32_t*)&a, *(uint32_t*)&b);
    }
}

// ---------------- fp16 mma GEMM: C[M,N] = A[M,K] * Bt[N,K]^T + bias ----------------
// BM=256, BN=128, BK=32. 256 threads = 8 warps (4m x 2n), warp 64x64.
// 3-stage cp.async ring. pitch 40 halves (80B, coprime 8 -> ldmatrix conflict-free).
#define AP 40
#define ATILE_B (256 * AP * 2)            // 20480 B
#define BTILE_B (128 * AP * 2)            // 10240 B
#define STAGE_B (ATILE_B + BTILE_B)       // 30720 B
#define GSMEM   (3 * STAGE_B)             // 92160 B

__device__ __forceinline__ void ld_chunk(const __half* Ab, const __half* Bb, int K,
                                         uint32_t stg, int tid)
{
    // A: 256 rows x 4 16B-units; B: 128 rows x 4 units
#pragma unroll
    for (int it = 0; it < 4; it++) {
        int c = tid + it * 256;
        int r = c >> 2, u = c & 3;
        cp16(stg + (uint32_t)(r * 80 + u * 16), Ab + (size_t)r * K + u * 8);
    }
#pragma unroll
    for (int it = 0; it < 2; it++) {
        int c = tid + it * 256;
        int r = c >> 2, u = c & 3;
        cp16(stg + ATILE_B + (uint32_t)(r * 80 + u * 16), Bb + (size_t)r * K + u * 8);
    }
}

__global__ __launch_bounds__(256, 1)
void gemm_h2(const __half* __restrict__ A, const __half* __restrict__ B,
             const float* __restrict__ bias, float* __restrict__ C32,
             __half* __restrict__ C16, int M, int N, int K, int relu)
{
    extern __shared__ __align__(16) char gsm[];
    const uint32_t sbase = smem_u32(gsm);
    const int tid = threadIdx.x, lane = tid & 31, wid = tid >> 5;
    const int grp = lane >> 2, tg = lane & 3;
    const int wm = wid >> 1, wn = wid & 1;        // warp tile (wm*64, wn*64)
    const int m0 = blockIdx.y * 256, n0 = blockIdx.x * 128;
    const __half* Ab = A + (size_t)m0 * K;
    const __half* Bb = B + (size_t)n0 * K;

    float acc[4][8][4];
#pragma unroll
    for (int i = 0; i < 4; i++)
#pragma unroll
        for (int j = 0; j < 8; j++)
#pragma unroll
            for (int r = 0; r < 4; r++) acc[i][j][r] = 0.f;

    const int nk = K >> 5;
    ld_chunk(Ab, Bb, K, sbase, tid);
    asm volatile("cp.async.commit_group;" ::: "memory");
    ld_chunk(Ab + 32, Bb + 32, K, sbase + STAGE_B, tid);
    asm volatile("cp.async.commit_group;" ::: "memory");

    for (int i = 0; i < nk; i++) {
        const int st = i % 3;
        if (i + 2 < nk)
            ld_chunk(Ab + (i + 2) * 32, Bb + (i + 2) * 32, K,
                     sbase + ((i + 2) % 3) * STAGE_B, tid);
        asm volatile("cp.async.commit_group;" ::: "memory");
        asm volatile("cp.async.wait_group 2;" ::: "memory");
        __syncthreads();

        const uint32_t a_s = sbase + st * STAGE_B;
        const uint32_t b_s = a_s + ATILE_B;
#pragma unroll
        for (int ks = 0; ks < 2; ks++) {
            uint32_t ra[4][4], rb[8][2];
#pragma unroll
            for (int mt = 0; mt < 4; mt++) {
                uint32_t ad = a_s + (uint32_t)((wm * 64 + mt * 16 + (lane & 15)) * 80
                                               + (ks * 2 + (lane >> 4)) * 16);
                LDSM4(ra[mt][0], ra[mt][1], ra[mt][2], ra[mt][3], ad);
            }
#pragma unroll
            for (int ntp = 0; ntp < 4; ntp++) {
                uint32_t r0, r1, r2, r3;
                uint32_t ad = b_s + (uint32_t)((wn * 64 + ntp * 16 + (lane & 15)) * 80
                                               + (ks * 2 + (lane >> 4)) * 16);
                LDSM4(r0, r1, r2, r3, ad);
                rb[2 * ntp][0] = r0;     rb[2 * ntp][1] = r2;
                rb[2 * ntp + 1][0] = r1; rb[2 * ntp + 1][1] = r3;
            }
#pragma unroll
            for (int mt = 0; mt < 4; mt++)
#pragma unroll
                for (int nt = 0; nt < 8; nt++)
                    mma_f16(acc[mt][nt], ra[mt], rb[nt]);
        }
        __syncthreads();
    }

    // epilogue
#pragma unroll
    for (int mt = 0; mt < 4; mt++) {
#pragma unroll
        for (int nt = 0; nt < 8; nt++) {
            int row = m0 + wm * 64 + mt * 16 + grp;
            int col = n0 + wn * 64 + nt * 8 + tg * 2;
            float b0 = bias[col], b1 = bias[col + 1];
            float v00 = acc[mt][nt][0] + b0, v01 = acc[mt][nt][1] + b1;
            float v10 = acc[mt][nt][2] + b0, v11 = acc[mt][nt][3] + b1;
            if (relu) {
                v00 = fmaxf(v00, 0.f); v01 = fmaxf(v01, 0.f);
                v10 = fmaxf(v10, 0.f); v11 = fmaxf(v11, 0.f);
            }
            if (C16) {
                *(__half2*)(C16 + (size_t)row * N + col)       = __floats2half2_rn(v00, v01);
                *(__half2*)(C16 + (size_t)(row + 8) * N + col) = __floats2half2_rn(v10, v11);
            } else {
                *(float2*)(C32 + (size_t)row * N + col)       = make_float2(v00, v01);
                *(float2*)(C32 + (size_t)(row + 8) * N + col) = make_float2(v10, v11);
            }
        }
    }
}

// ---------------- fp16 mma flash attention ----------------
// CTA: 256 threads (8 warps), 128 q-rows, k-tiles of 64. DH=64.
// smem pitch 144B/row (9*16B, coprime 8). Q: 128*144, K/V double-buffered 64*144 each.
#define FQB 18432
#define FKV 9216
#define FLASH_SMEM (FQB + 2 * 2 * FKV)

__global__ __launch_bounds__(256) void flash_h(const __half* __restrict__ qkv,
                                               __half* __restrict__ attn)
{
    extern __shared__ __align__(16) char fsm[];
    const uint32_t sbase = smem_u32(fsm);
    const int tid = threadIdx.x, lane = tid & 31, wid = tid >> 5;
    const int grp = lane >> 2, tg = lane & 3;
    const int b = blockIdx.y >> 4, h = blockIdx.y & 15;
    const int q0 = blockIdx.x * 128;

    const __half* Qg = qkv + ((size_t)(b * SEQ + q0)) * QKVN + h * DHEAD;
    const __half* Kg = qkv + (size_t)b * SEQ * QKVN + 1024 + h * DHEAD;
    const __half* Vg = Kg + 1024;

#pragma unroll
    for (int it = 0; it < 4; it++) {
        int c = tid + it * 256;
        int r = c >> 3, u = c & 7;
        cp16(sbase + (uint32_t)(r * 144 + u * 16), Qg + (size_t)r * QKVN + u * 8);
    }
    asm volatile("cp.async.commit_group;" ::: "memory");

    {
#pragma unroll
        for (int it = 0; it < 4; it++) {
            int c = tid + it * 256;
            int mv = c >> 9, cc = c & 511;
            int r = cc >> 3, u = cc & 7;
            const __half* src = (mv ? Vg : Kg) + (size_t)r * QKVN + u * 8;
            cp16(sbase + FQB + (uint32_t)(mv * FKV + r * 144 + u * 16), src);
        }
        asm volatile("cp.async.commit_group;" ::: "memory");
    }

    uint32_t qf[4][4];
    float oacc[8][4];
    float m_run[2] = {-1e30f, -1e30f}, l_run[2] = {0.f, 0.f};
#pragma unroll
    for (int nt = 0; nt < 8; nt++)
#pragma unroll
        for (int j = 0; j < 4; j++) oacc[nt][j] = 0.f;

    const int NT = SEQ / 64;
    for (int kt = 0; kt < NT; kt++) {
        const int buf = kt & 1;
        if (kt + 1 < NT) {
#pragma unroll
            for (int it = 0; it < 4; it++) {
                int c = tid + it * 256;
                int mv = c >> 9, cc = c & 511;
                int r = cc >> 3, u = cc & 7;
                const __half* src = (mv ? Vg : Kg) + (size_t)((kt + 1) * 64 + r) * QKVN + u * 8;
                cp16(sbase + FQB + (uint32_t)((1 - buf) * 2 * FKV + mv * FKV + r * 144 + u * 16), src);
            }
            asm volatile("cp.async.commit_group;" ::: "memory");
            asm volatile("cp.async.wait_group 1;" ::: "memory");
        } else {
            asm volatile("cp.async.wait_group 0;" ::: "memory");
        }
        __syncthreads();

        if (kt == 0) {
#pragma unroll
            for (int ks = 0; ks < 4; ks++) {
                uint32_t ad = sbase + (uint32_t)((wid * 16 + (lane & 15)) * 144
                                                 + (ks * 2 + (lane >> 4)) * 16);
                LDSM4(qf[ks][0], qf[ks][1], qf[ks][2], qf[ks][3], ad);
            }
        }

        float sacc[8][4];
#pragma unroll
        for (int nt = 0; nt < 8; nt++)
#pragma unroll
            for (int j = 0; j < 4; j++) sacc[nt][j] = 0.f;

        const uint32_t kbB = sbase + FQB + (uint32_t)(buf * 2 * FKV);
#pragma unroll
        for (int ks = 0; ks < 4; ks++) {
#pragma unroll
            for (int ntp = 0; ntp < 4; ntp++) {
                uint32_t r0, r1, r2, r3;
                uint32_t ad = kbB + (uint32_t)((ntp * 16 + (lane & 15)) * 144
                                               + (ks * 2 + (lane >> 4)) * 16);
                LDSM4(r0, r1, r2, r3, ad);
                uint32_t be[2] = {r0, r2}, bo[2] = {r1, r3};
                mma_f16(sacc[2 * ntp],     qf[ks], be);
                mma_f16(sacc[2 * ntp + 1], qf[ks], bo);
            }
        }

#pragma unroll
        for (int r = 0; r < 2; r++) {
            const int j = r * 2;
            float mx = -1e30f;
#pragma unroll
            for (int nt = 0; nt < 8; nt++)
                mx = fmaxf(mx, fmaxf(sacc[nt][j], sacc[nt][j + 1]));
            mx = fmaxf(mx, __shfl_xor_sync(0xffffffffu, mx, 1));
            mx = fmaxf(mx, __shfl_xor_sync(0xffffffffu, mx, 2));
            float mnew = fmaxf(m_run[r], mx);
            float corr = exp2f(m_run[r] - mnew);
            float ls = 0.f;
#pragma unroll
            for (int nt = 0; nt < 8; nt++) {
                float p0 = exp2f(sacc[nt][j] - mnew);
                float p1 = exp2f(sacc[nt][j + 1] - mnew);
                sacc[nt][j] = p0; sacc[nt][j + 1] = p1;
                ls += p0 + p1;
            }
            ls += __shfl_xor_sync(0xffffffffu, ls, 1);
            ls += __shfl_xor_sync(0xffffffffu, ls, 2);
            m_run[r] = mnew;
            l_run[r] = l_run[r] * corr + ls;
#pragma unroll
            for (int nt = 0; nt < 8; nt++) {
                oacc[nt][j] *= corr; oacc[nt][j + 1] *= corr;
            }
        }

        uint32_t pa[4][4];
#pragma unroll
        for (int kp = 0; kp < 4; kp++) {
            pa[kp][0] = h2pack(sacc[2 * kp][0],     sacc[2 * kp][1]);
            pa[kp][1] = h2pack(sacc[2 * kp][2],     sacc[2 * kp][3]);
            pa[kp][2] = h2pack(sacc[2 * kp + 1][0], sacc[2 * kp + 1][1]);
            pa[kp][3] = h2pack(sacc[2 * kp + 1][2], sacc[2 * kp + 1][3]);
        }

        const uint32_t vbB = kbB + FKV;
#pragma unroll
        for (int kp = 0; kp < 4; kp++) {
#pragma unroll
            for (int ntp = 0; ntp < 4; ntp++) {
                uint32_t r0, r1, r2, r3;
                uint32_t ad = vbB + (uint32_t)((kp * 16 + (lane & 15)) * 144
                                               + (ntp * 2 + (lane >> 4)) * 16);
                LDSM4T(r0, r1, r2, r3, ad);
                uint32_t be[2] = {r0, r1}, bo[2] = {r2, r3};
                mma_f16(oacc[2 * ntp],     pa[kp], be);
                mma_f16(oacc[2 * ntp + 1], pa[kp], bo);
            }
        }
        __syncthreads();
    }

    const float inv0 = 1.f / l_run[0], inv1 = 1.f / l_run[1];
    const size_t row0 = (size_t)(b * SEQ + q0 + wid * 16 + grp);
#pragma unroll
    for (int nt = 0; nt < 8; nt++) {
        int col = h * DHEAD + nt * 8 + tg * 2;
        *(__half2*)(attn + row0 * DMODEL + col) =
            __floats2half2_rn(oacc[nt][0] * inv0, oacc[nt][1] * inv0);
        *(__half2*)(attn + (row0 + 8) * DMODEL + col) =
            __floats2half2_rn(oacc[nt][2] * inv1, oacc[nt][3] * inv1);
    }
}

// ---------------- residual add + LayerNorm (+ optional half copy) ----------------
__global__ __launch_bounds__(256) void add_ln(const float* __restrict__ a,
                                              const float* __restrict__ resid,
                                              const float* __restrict__ g,
                                              const float* __restrict__ bb,
                                              float* __restrict__ out,
                                              __half* __restrict__ out_h)
{
    const int row = blockIdx.x;
    const int tid = threadIdx.x;
    const float* ar = a     + (size_t)row * DMODEL;
    const float* rr = resid + (size_t)row * DMODEL;

    float v[4], s = 0.f, sq = 0.f;
#pragma unroll
    for (int u = 0; u < 4; u++) {
        int c = u * 256 + tid;
        float t = ar[c] + rr[c];
        v[u] = t; s += t; sq += t * t;
    }
#pragma unroll
    for (int mm = 16; mm; mm >>= 1) {
        s  += __shfl_xor_sync(0xffffffffu, s, mm);
        sq += __shfl_xor_sync(0xffffffffu, sq, mm);
    }
    __shared__ float rs[8], rq[8];
    int w = tid >> 5, l = tid & 31;
    if (l == 0) { rs[w] = s; rq[w] = sq; }
    __syncthreads();
    s = 0.f; sq = 0.f;
#pragma unroll
    for (int i = 0; i < 8; i++) { s += rs[i]; sq += rq[i]; }

    float mean = s * (1.f / DMODEL);
    float var  = sq * (1.f / DMODEL) - mean * mean;
    float rstd = rsqrtf(var + 1e-5f);
    float* orow = out + (size_t)row * DMODEL;
#pragma unroll
    for (int u = 0; u < 4; u++) {
        int c = u * 256 + tid;
        float ov = (v[u] - mean) * rstd * g[c] + bb[c];
        orow[c] = ov;
        if (out_h) out_h[(size_t)row * DMODEL + c] = __float2half(ov);
    }
}

// ---------------- launch ----------------
extern "C" void kernel_launch(void* const* d_in, const int* in_sizes, int n_in,
                              void* d_out, int out_size)
{
    const float* x    = (const float*)d_in[0];
    const float* wq   = (const float*)d_in[1];
    const float* bq   = (const float*)d_in[2];
    const float* wk   = (const float*)d_in[3];
    const float* bk   = (const float*)d_in[4];
    const float* wv   = (const float*)d_in[5];
    const float* bv   = (const float*)d_in[6];
    const float* wo   = (const float*)d_in[7];
    const float* bo   = (const float*)d_in[8];
    const float* ln1g = (const float*)d_in[9];
    const float* ln1b = (const float*)d_in[10];
    const float* w1   = (const float*)d_in[11];
    const float* b1   = (const float*)d_in[12];
    const float* w2   = (const float*)d_in[13];
    const float* b2   = (const float*)d_in[14];
    const float* ln2g = (const float*)d_in[15];
    const float* ln2b = (const float*)d_in[16];
    float* out = (float*)d_out;

    __half *wqkvT, *woT, *w1T, *w2T, *xh, *qkvh, *attnh, *yh, *ff1h;
    float *bqkv, *t1, *y, *ff2;
    cudaGetSymbolAddress((void**)&wqkvT, g_wqkvT);
    cudaGetSymbolAddress((void**)&bqkv,  g_bqkv);
    cudaGetSymbolAddress((void**)&woT,   g_woT);
    cudaGetSymbolAddress((void**)&w1T,   g_w1T);
    cudaGetSymbolAddress((void**)&w2T,   g_w2T);
    cudaGetSymbolAddress((void**)&xh,    g_xh);
    cudaGetSymbolAddress((void**)&qkvh,  g_qkvh);
    cudaGetSymbolAddress((void**)&attnh, g_attnh);
    cudaGetSymbolAddress((void**)&t1,    g_t1);
    cudaGetSymbolAddress((void**)&y,     g_y);
    cudaGetSymbolAddress((void**)&yh,    g_yh);
    cudaGetSymbolAddress((void**)&ff1h,  g_ff1h);
    cudaGetSymbolAddress((void**)&ff2,   g_ff2);

    cudaFuncSetAttribute(flash_h, cudaFuncAttributeMaxDynamicSharedMemorySize, FLASH_SMEM);
    cudaFuncSetAttribute(gemm_h2, cudaFuncAttributeMaxDynamicSharedMemorySize, GSMEM);

    // prep
    pack_wqkv_t<<<dim3(DHEAD / 32, DMODEL / 32, NHEAD), dim3(32, 8)>>>(wq, wk, wv);
    pack_bqkv<<<(NHEAD * DHEAD + 255) / 256, 256>>>(bq, bk, bv);
    transpose_h<<<dim3(DMODEL / 32, DMODEL / 32), dim3(32, 8)>>>(wo, woT, DMODEL, DMODEL);
    transpose_h<<<dim3(FFDIM / 32, DMODEL / 32), dim3(32, 8)>>>(w1, w1T, DMODEL, FFDIM);
    transpose_h<<<dim3(DMODEL / 32, FFDIM / 32), dim3(32, 8)>>>(w2, w2T, FFDIM, DMODEL);
    f2h_copy<<<(BS * DMODEL / 4 + 255) / 256, 256>>>(x, xh, BS * DMODEL / 4);

    // 1) QKV projection -> half (Q pre-scaled by log2e/8 via weights)
    gemm_h2<<<dim3(QKVN / 128, BS / 256), 256, GSMEM>>>(xh, wqkvT, bqkv, nullptr, qkvh,
                                                        BS, QKVN, DMODEL, 0);
    // 2) flash attention -> half
    flash_h<<<dim3(SEQ / 128, BATCH * NHEAD), 256, FLASH_SMEM>>>(qkvh, attnh);
    // 3) output projection -> fp32
    gemm_h2<<<dim3(DMODEL / 128, BS / 256), 256, GSMEM>>>(attnh, woT, bo, t1, nullptr,
                                                          BS, DMODEL, DMODEL, 0);
    // 4) residual + LN1 -> y (fp32) + yh (half)
    add_ln<<<BS, 256>>>(t1, x, ln1g, ln1b, y, yh);
    // 5) FFN up (relu) -> half
    gemm_h2<<<dim3(FFDIM / 128, BS / 256), 256, GSMEM>>>(yh, w1T, b1, nullptr, ff1h,
                                                         BS, FFDIM, DMODEL, 1);
    // 6) FFN down -> fp32
    gemm_h2<<<dim3(DMODEL / 128, BS / 256), 256, GSMEM>>>(ff1h, w2T, b2, ff2, nullptr,
                                                          BS, DMODEL, FFDIM, 0);
    // 7) residual + LN2 -> final output
    add_ln<<<BS, 256>>>(ff2, y, ln2g, ln2b, out, nullptr);
}